// round 4
// baseline (speedup 1.0000x reference)
#include <cuda_runtime.h>
#include <stdint.h>

// Multiplexer: out[b, :] = full_input[b, idx[b]*64 : (idx[b]+1)*64]
// BATCH = 262144, OUTPUT_DIM = 64, NB_CTRL_SIG = 16 (row width 1024 f32)

#define OUTPUT_DIM 64
#define ROW_WIDTH  1024               // OUTPUT_DIM * NB_CTRL_SIG
#define ROW_VECS   (ROW_WIDTH / 4)    // 256 float4 per input row
#define OUT_VECS   (OUTPUT_DIM / 4)   // 16 float4 per output row
#define THREADS    256
#define ROWS_PER_THREAD 8
#define ROWS_PER_BLOCK  (THREADS / 16 * ROWS_PER_THREAD)  // 128

__global__ void __launch_bounds__(THREADS)
mux_gather8_kernel(const float4* __restrict__ in,      // [BATCH, 256] float4 view
                   const int4*   __restrict__ indices, // [BATCH/4] int4 view
                   float4*       __restrict__ out,     // [BATCH, 16] float4 view
                   int batch)
{
    int tid  = threadIdx.x;
    int g    = tid >> 4;          // group 0..15; each group handles 8 consecutive rows
    int sub  = tid & 15;          // float4 slot within a row

    int row0 = blockIdx.x * ROWS_PER_BLOCK + g * ROWS_PER_THREAD;
    if (row0 >= batch) return;

    // Two independent vectorized index loads cover all 8 rows (row0 is 8-aligned).
    int4 iv0 = __ldg(&indices[(row0 >> 2) + 0]);
    int4 iv1 = __ldg(&indices[(row0 >> 2) + 1]);
    int idx[8] = {iv0.x, iv0.y, iv0.z, iv0.w, iv1.x, iv1.y, iv1.z, iv1.w};

    // 8 independent gather loads issued back-to-back — MLP_eff ~ 8.
    float4 v[8];
#pragma unroll
    for (int i = 0; i < 8; i++) {
        const float4* src = in + (size_t)(row0 + i) * ROW_VECS
                               + idx[i] * OUT_VECS + sub;
        v[i] = __ldcs(src);
    }

#pragma unroll
    for (int i = 0; i < 8; i++) {
        __stcs(out + (size_t)(row0 + i) * OUT_VECS + sub, v[i]);
    }
}

extern "C" void kernel_launch(void* const* d_in, const int* in_sizes, int n_in,
                              void* d_out, int out_size)
{
    const float* full_input = (const float*)d_in[0];
    const int*   indices    = (const int*)d_in[1];
    float*       out        = (float*)d_out;

    int batch = in_sizes[0] / ROW_WIDTH;   // 262144

    int blocks = (batch + ROWS_PER_BLOCK - 1) / ROWS_PER_BLOCK;  // 2048
    mux_gather8_kernel<<<blocks, THREADS>>>(
        (const float4*)full_input, (const int4*)indices, (float4*)out, batch);
}

// round 6
// speedup vs baseline: 1.0824x; 1.0824x over previous
#include <cuda_runtime.h>
#include <stdint.h>

// Multiplexer: out[b, :] = full_input[b, idx[b]*64 : (idx[b]+1)*64]
// BATCH = 262144, OUTPUT_DIM = 64, NB_CTRL_SIG = 16 (row width 1024 f32)
//
// Gather reads via LDG.128 (own the L1tex wavefront queue);
// stores staged in smem and flushed with cp.async.bulk (async proxy,
// bypasses the L1tex FIFO) — 2KB contiguous per warp.

#define OUTPUT_DIM 64
#define ROW_WIDTH  1024               // OUTPUT_DIM * NB_CTRL_SIG
#define ROW_VECS   (ROW_WIDTH / 4)    // 256 float4 per input row
#define OUT_VECS   (OUTPUT_DIM / 4)   // 16 float4 per output row
#define THREADS    256
#define WARPS      (THREADS / 32)     // 8
#define ROWS_PER_THREAD 4
#define ROWS_PER_WARP   8             // 2 groups of 16 threads x 4 rows
#define ROWS_PER_BLOCK  (WARPS * ROWS_PER_WARP)   // 64
#define BYTES_PER_WARP  (ROWS_PER_WARP * OUTPUT_DIM * 4)  // 2048

__global__ void __launch_bounds__(THREADS)
mux_gather_bulkstore_kernel(const float4* __restrict__ in,      // [BATCH, 256] f4
                            const int4*   __restrict__ indices, // [BATCH/4] int4
                            float*        __restrict__ out,     // [BATCH, 64]
                            int batch)
{
    __shared__ __align__(128) float4 stage[ROWS_PER_BLOCK * OUT_VECS];  // 16 KB

    int tid  = threadIdx.x;
    int wid  = tid >> 5;
    int lane = tid & 31;
    int g    = tid >> 4;          // group 0..15 within block; 4 rows each
    int sub  = tid & 15;          // float4 slot within a row

    int row0 = blockIdx.x * ROWS_PER_BLOCK + g * ROWS_PER_THREAD;
    if (row0 < batch) {
        // One int4 load covers this thread's 4 indices (row0 is 4-aligned).
        int4 iv = __ldg(&indices[row0 >> 2]);
        int idx[4] = {iv.x, iv.y, iv.z, iv.w};

        // 4 independent gather loads, back-to-back (MLP ~ 4/thread).
        float4 v[4];
#pragma unroll
        for (int i = 0; i < 4; i++) {
            const float4* src = in + (size_t)(row0 + i) * ROW_VECS
                                   + idx[i] * OUT_VECS + sub;
            v[i] = __ldcs(src);
        }

        // Stage into smem: row-local layout, linear in row order.
        int rloc = g * ROWS_PER_THREAD - wid * 0;  // rows local to BLOCK
        int row_local = g * ROWS_PER_THREAD;       // 0..60 step 4
#pragma unroll
        for (int i = 0; i < 4; i++) {
            stage[(row_local + i) * OUT_VECS + sub] = v[i];
        }
        (void)rloc;
    }

    // Warp-level flush: each warp owns rows [wid*8, wid*8+8) = 2 KB contiguous
    // in both smem and gmem.
    __syncwarp();
    // Make smem writes visible to the async proxy.
    asm volatile("fence.proxy.async.shared::cta;" ::: "memory");

    int warp_row0 = blockIdx.x * ROWS_PER_BLOCK + wid * ROWS_PER_WARP;
    if (lane == 0 && warp_row0 < batch) {
        uint32_t saddr = (uint32_t)__cvta_generic_to_shared(
            &stage[wid * ROWS_PER_WARP * OUT_VECS]);
        float* gptr = out + (size_t)warp_row0 * OUTPUT_DIM;
        asm volatile(
            "cp.async.bulk.global.shared::cta.bulk_group [%0], [%1], %2;"
            :: "l"(gptr), "r"(saddr), "r"(BYTES_PER_WARP) : "memory");
        asm volatile("cp.async.bulk.commit_group;" ::: "memory");
        asm volatile("cp.async.bulk.wait_group 0;" ::: "memory");
    }
}

extern "C" void kernel_launch(void* const* d_in, const int* in_sizes, int n_in,
                              void* d_out, int out_size)
{
    const float* full_input = (const float*)d_in[0];
    const int*   indices    = (const int*)d_in[1];
    float*       out        = (float*)d_out;

    int batch = in_sizes[0] / ROW_WIDTH;   // 262144

    int blocks = (batch + ROWS_PER_BLOCK - 1) / ROWS_PER_BLOCK;  // 4096
    mux_gather_bulkstore_kernel<<<blocks, THREADS>>>(
        (const float4*)full_input, (const int4*)indices, out, batch);
}